// round 2
// baseline (speedup 1.0000x reference)
#include <cuda_runtime.h>
#include <cuda_bf16.h>

// Problem constants (fixed by the dataset shapes)
#define BH      64        // B*H = 8*8
#define SEQ     16384     // S
#define DV      64        // value head dim
#define NSPLIT  16        // split-S factor for pass 1
#define SCHUNK  (SEQ / NSPLIT)   // 1024 rows per block
#define PSTRIDE 80        // per-(bh,split) scratch stride in floats (16B-aligned: 320 B)

// Scratch: per-(bh,split) partials: 64 ktv floats + k2 + q2 (+ pad to 80)
__device__ __align__(16) float g_part[BH * NSPLIT * PSTRIDE];
__device__ __align__(16) float g_coef[BH * DV];

// ---------------------------------------------------------------------------
// Pass 1: per (bh, split) compute partial K^T V (64-wide), sum K^2, sum Q^2.
// 256 threads: eg = tid&15 -> which float4 of the 64-wide row
//              rg = tid>>4 -> row stride group
// ---------------------------------------------------------------------------
__global__ __launch_bounds__(256) void ktv_reduce_kernel(
    const float* __restrict__ Q,
    const float* __restrict__ K,
    const float* __restrict__ V)
{
    const int bh    = blockIdx.x;   // 0..63
    const int split = blockIdx.y;   // 0..15
    const int tid   = threadIdx.x;
    const int eg    = tid & 15;
    const int rg    = tid >> 4;

    const float* __restrict__ Kp = K + (size_t)bh * SEQ + (size_t)split * SCHUNK;
    const float* __restrict__ Qp = Q + (size_t)bh * SEQ + (size_t)split * SCHUNK;
    const float4* __restrict__ Vp =
        (const float4*)(V + (size_t)bh * SEQ * DV + (size_t)split * SCHUNK * DV);

    // Accumulate k * v over this thread's rows (rg, rg+16, ...)
    float4 acc = make_float4(0.f, 0.f, 0.f, 0.f);
#pragma unroll 4
    for (int s = rg; s < SCHUNK; s += 16) {
        float  k = __ldg(Kp + s);
        float4 v = Vp[(size_t)s * 16 + eg];
        acc.x += k * v.x;
        acc.y += k * v.y;
        acc.z += k * v.z;
        acc.w += k * v.w;
    }

    // Norm partials: each thread strides over the chunk
    float k2 = 0.f, q2 = 0.f;
#pragma unroll 2
    for (int s = tid; s < SCHUNK; s += 256) {
        float k = __ldg(Kp + s);
        float q = __ldg(Qp + s);
        k2 += k * k;
        q2 += q * q;
    }

    __shared__ float4 sacc[256];
    __shared__ float2 skq[256];
    sacc[tid] = acc;
    skq[tid]  = make_float2(k2, q2);
    __syncthreads();

    // Tree-reduce. Strides are multiples of 16, so sacc reduction combines
    // threads with identical eg (same e-column group). Deterministic order.
#pragma unroll
    for (int stride = 128; stride >= 16; stride >>= 1) {
        if (tid < stride) {
            float4 a = sacc[tid], b = sacc[tid + stride];
            a.x += b.x; a.y += b.y; a.z += b.z; a.w += b.w;
            sacc[tid] = a;
            float2 p = skq[tid], q = skq[tid + stride];
            p.x += q.x; p.y += q.y;
            skq[tid] = p;
        }
        __syncthreads();
    }
    // Finish the scalar (k2,q2) reduction below stride 16 within warp 0
    if (tid < 16) {
        float2 p = skq[tid];
#pragma unroll
        for (int stride = 8; stride >= 1; stride >>= 1) {
            p.x += __shfl_down_sync(0xFFFF, p.x, stride, 16);
            p.y += __shfl_down_sync(0xFFFF, p.y, stride, 16);
        }
        float* base = g_part + (size_t)(bh * NSPLIT + split) * PSTRIDE;
        ((float4*)base)[tid] = sacc[tid];   // ktv[4*tid .. 4*tid+3], base is 320B-strided -> 16B aligned
        if (tid == 0) {
            base[64] = p.x;
            base[65] = p.y;
        }
    }
}

// ---------------------------------------------------------------------------
// Pass 2: fold split partials and the norm scale into 64 coefficients per bh.
//   coef[bh][e] = (sum_split ktv[e]) / (||K|| * ||Q||)
// 64 blocks x 64 threads; each thread independently re-sums the (tiny) norm
// partials -> no sync needed, deterministic.
// ---------------------------------------------------------------------------
__global__ __launch_bounds__(64) void finalize_kernel()
{
    const int bh = blockIdx.x;
    const int e  = threadIdx.x;
    float ktv = 0.f, k2 = 0.f, q2 = 0.f;
#pragma unroll
    for (int sp = 0; sp < NSPLIT; sp++) {
        const float* p = g_part + (size_t)(bh * NSPLIT + sp) * PSTRIDE;
        ktv += p[e];
        k2  += p[64];
        q2  += p[65];
    }
    g_coef[bh * DV + e] = ktv * rsqrtf(k2) * rsqrtf(q2);
}

// ---------------------------------------------------------------------------
// Pass 3: out[bh, s, e] = Q[bh, s] * coef[bh, e]   (streaming float4 stores)
// grid: (SEQ/64, BH); block: 256 threads -> 16 rows per iteration, 4 iters.
// ---------------------------------------------------------------------------
__global__ __launch_bounds__(256) void out_kernel(
    const float* __restrict__ Q,
    float* __restrict__ out)
{
    const int bh = blockIdx.y;
    const int s0 = blockIdx.x * 64;
    const int tid = threadIdx.x;
    const int eg  = tid & 15;
    const int rg  = tid >> 4;

    __shared__ float4 scoef[16];
    if (tid < 16) scoef[tid] = ((const float4*)(g_coef + bh * DV))[tid];
    __syncthreads();

    const float* __restrict__ Qp = Q + (size_t)bh * SEQ + s0;
    float4* __restrict__ Op =
        (float4*)(out + (size_t)bh * SEQ * DV + (size_t)s0 * DV);

    const float4 c = scoef[eg];
#pragma unroll
    for (int r = rg; r < 64; r += 16) {
        float q = __ldg(Qp + r);
        Op[(size_t)r * 16 + eg] = make_float4(q * c.x, q * c.y, q * c.z, q * c.w);
    }
}

extern "C" void kernel_launch(void* const* d_in, const int* in_sizes, int n_in,
                              void* d_out, int out_size)
{
    const float* Q = (const float*)d_in[0];
    const float* K = (const float*)d_in[1];
    const float* V = (const float*)d_in[2];
    float* out = (float*)d_out;

    dim3 g1(BH, NSPLIT);
    ktv_reduce_kernel<<<g1, 256>>>(Q, K, V);

    finalize_kernel<<<BH, 64>>>();

    dim3 g3(SEQ / 64, BH);
    out_kernel<<<g3, 256>>>(Q, out);
}

// round 5
// speedup vs baseline: 1.0912x; 1.0912x over previous
#include <cuda_runtime.h>
#include <cuda_bf16.h>

// Problem constants (fixed by the dataset shapes)
#define BH      64        // B*H = 8*8
#define SEQ     16384     // S
#define DV      64        // value head dim
#define NSPLIT  16        // split-S factor for pass 1
#define SCHUNK  (SEQ / NSPLIT)   // 1024 rows per block
#define PSTRIDE 80        // per-(bh,split) scratch stride in floats (320 B, 16B-aligned)

// Scratch: per-(bh,split) partials: 64 ktv floats + k2 + q2 (+ pad to 80)
__device__ __align__(16) float g_part[BH * NSPLIT * PSTRIDE];

// ---------------------------------------------------------------------------
// Pass 1: per (bh, split) compute partial K^T V (64-wide), sum K^2, sum Q^2.
// 256 threads: eg = tid&15 -> which float4 of the 64-wide row
//              rg = tid>>4 -> row stride group
// ---------------------------------------------------------------------------
__global__ __launch_bounds__(256) void ktv_reduce_kernel(
    const float* __restrict__ Q,
    const float* __restrict__ K,
    const float* __restrict__ V)
{
    const int bh    = blockIdx.x;   // 0..63
    const int split = blockIdx.y;   // 0..15
    const int tid   = threadIdx.x;
    const int eg    = tid & 15;
    const int rg    = tid >> 4;

    const float* __restrict__ Kp = K + (size_t)bh * SEQ + (size_t)split * SCHUNK;
    const float* __restrict__ Qp = Q + (size_t)bh * SEQ + (size_t)split * SCHUNK;
    const float4* __restrict__ Vp =
        (const float4*)(V + (size_t)bh * SEQ * DV + (size_t)split * SCHUNK * DV);

    // Accumulate k * v over this thread's rows (rg, rg+16, ...).
    // Unroll 8 -> 8 outstanding LDG.128 per thread (MLP), streaming loads of V.
    float4 acc = make_float4(0.f, 0.f, 0.f, 0.f);
#pragma unroll 8
    for (int s = rg; s < SCHUNK; s += 16) {
        float  k = __ldg(Kp + s);
        float4 v = __ldcs(Vp + (size_t)s * 16 + eg);   // V is read-once: evict-first
        acc.x += k * v.x;
        acc.y += k * v.y;
        acc.z += k * v.z;
        acc.w += k * v.w;
    }

    // Norm partials: each thread strides over the chunk
    float k2 = 0.f, q2 = 0.f;
#pragma unroll 4
    for (int s = tid; s < SCHUNK; s += 256) {
        float k = __ldg(Kp + s);
        float q = __ldg(Qp + s);
        k2 += k * k;
        q2 += q * q;
    }

    __shared__ float4 sacc[256];
    __shared__ float2 skq[256];
    sacc[tid] = acc;
    skq[tid]  = make_float2(k2, q2);
    __syncthreads();

    // Tree-reduce. Strides are multiples of 16, so sacc reduction combines
    // threads with identical eg (same e-column group). Deterministic order.
#pragma unroll
    for (int stride = 128; stride >= 16; stride >>= 1) {
        if (tid < stride) {
            float4 a = sacc[tid], b = sacc[tid + stride];
            a.x += b.x; a.y += b.y; a.z += b.z; a.w += b.w;
            sacc[tid] = a;
            float2 p = skq[tid], q = skq[tid + stride];
            p.x += q.x; p.y += q.y;
            skq[tid] = p;
        }
        __syncthreads();
    }
    // Finish the scalar (k2,q2) reduction below stride 16 within warp 0
    if (tid < 16) {
        float2 p = skq[tid];
#pragma unroll
        for (int stride = 8; stride >= 1; stride >>= 1) {
            p.x += __shfl_down_sync(0xFFFF, p.x, stride, 16);
            p.y += __shfl_down_sync(0xFFFF, p.y, stride, 16);
        }
        float* base = g_part + (size_t)(bh * NSPLIT + split) * PSTRIDE;
        ((float4*)base)[tid] = sacc[tid];   // 320B stride -> 16B aligned
        if (tid == 0) {
            base[64] = p.x;
            base[65] = p.y;
        }
    }
}

// ---------------------------------------------------------------------------
// Pass 2 (fused finalize + broadcast write):
//   coef[e] = (sum_split ktv[e]) * rsqrt(sum k2) * rsqrt(sum q2)
//   out[bh, s, e] = Q[bh, s] * coef[e]
// grid: (SEQ/256, BH); block 256. Each block covers 256 rows.
// Coefficient recompute per block reads 16*PSTRIDE floats from L2 (trivial).
// ---------------------------------------------------------------------------
__global__ __launch_bounds__(256) void out_kernel(
    const float* __restrict__ Q,
    float* __restrict__ out)
{
    const int bh  = blockIdx.y;
    const int s0  = blockIdx.x * 256;
    const int tid = threadIdx.x;
    const int eg  = tid & 15;
    const int rg  = tid >> 4;

    __shared__ float scoef[DV];
    if (tid < DV) {
        float ktv = 0.f, k2 = 0.f, q2 = 0.f;
#pragma unroll
        for (int sp = 0; sp < NSPLIT; sp++) {
            const float* p = g_part + (size_t)(bh * NSPLIT + sp) * PSTRIDE;
            ktv += __ldg(p + tid);
            k2  += __ldg(p + 64);
            q2  += __ldg(p + 65);
        }
        scoef[tid] = ktv * rsqrtf(k2) * rsqrtf(q2);
    }
    __syncthreads();

    const float4 c = ((const float4*)scoef)[eg];
    const float* __restrict__ Qp = Q + (size_t)bh * SEQ + s0;
    float4* __restrict__ Op =
        (float4*)(out + (size_t)bh * SEQ * DV + (size_t)s0 * DV);

#pragma unroll 8
    for (int r = rg; r < 256; r += 16) {
        float q = __ldg(Qp + r);
        __stcs(Op + (size_t)r * 16 + eg,
               make_float4(q * c.x, q * c.y, q * c.z, q * c.w));  // write-once: evict-first
    }
}

extern "C" void kernel_launch(void* const* d_in, const int* in_sizes, int n_in,
                              void* d_out, int out_size)
{
    const float* Q = (const float*)d_in[0];
    const float* K = (const float*)d_in[1];
    const float* V = (const float*)d_in[2];
    float* out = (float*)d_out;

    dim3 g1(BH, NSPLIT);
    ktv_reduce_kernel<<<g1, 256>>>(Q, K, V);

    dim3 g2(SEQ / 256, BH);
    out_kernel<<<g2, 256>>>(Q, out);
}